// round 13
// baseline (speedup 1.0000x reference)
#include <cuda_runtime.h>
#include <cstdint>

// ---------------------------------------------------------------------------
// GNN message passing, 50000 nodes / 400000 edges / HIDDEN=256 / 3 layers.
// tf32 mma.sync.m16n8k8. R13 GEMM: CTA 128x64, warp tile 32x32, 256 thr,
// 3 CTA/SM (24 warps/SM, ~80 regs) — direct test of the latency-bound
// hypothesis (R10: barriers neutral; R11: fewer warps much worse).
// 2-stage cp.async (55.5KB smem/CTA). All operands pre-rounded to tf32.
// PaPb merged (N=512 via repacked Wab) + aggr zeroing folded into epilogue.
// Scatter fused into edge GEMM epilogue (red.global.add.v2.f32).
// hidden1 ET=32 2x-unrolled; copy_h folded into last up2 (dup store).
// ---------------------------------------------------------------------------

#define NN 50000
#define NE 400000

__device__ float g_Hcat[(size_t)NN * 512];   // [h | aggr], h tf32-rounded
__device__ float g_P[(size_t)NN * 512];      // [Pa | Pb] (fp32)
__device__ float g_M1[(size_t)NE * 256];     // hidden1 per edge, tf32-rounded
__device__ float g_U[(size_t)NN * 256];      // update hidden, tf32-rounded
__device__ float g_E[(size_t)NE * 32];       // projected edge features
__device__ float g_T[(size_t)NN * 128];      // token head hidden
__device__ float g_Xc[(size_t)NN * 128];     // x, tf32-rounded
__device__ float g_Wc[1245184];              // all weights, tf32-rounded

// g_Wc offsets (floats)
#define WC_MSGAB 0                           // 3*256*512 (repacked W1ab)
#define WC_MSG2  393216                      // 3*256*256
#define WC_UP1   589824                      // 3*512*256
#define WC_UP2   983040                      // 3*256*256
#define WC_NODE  1179648                     // 128*256
#define WC_TOK   1212416                     // 256*128

__device__ __forceinline__ unsigned f2tf(float f) {
    unsigned u;
    asm("cvt.rna.tf32.f32 %0, %1;" : "=r"(u) : "f"(f));
    return u;
}
__device__ __forceinline__ float f2tf_f(float f) {
    return __uint_as_float(f2tf(f));
}
__device__ __forceinline__ uint32_t smem_u32(const void* p) {
    return (uint32_t)__cvta_generic_to_shared(p);
}
__device__ __forceinline__ void cp16(uint32_t dst, const void* src) {
    asm volatile("cp.async.cg.shared.global [%0], [%1], 16;" :: "r"(dst), "l"(src));
}
__device__ __forceinline__ void cp_commit() {
    asm volatile("cp.async.commit_group;" ::: "memory");
}

// smem layout (words): A bufs 2*4608 @0, B bufs 2*2304 @9216, bias 64 @13824
#define AW 36
#define ABUF 4608                            // 128 rows * 36
#define BW 72
#define BBUF 2304                            // 32 rows * 72
#define BOFF 9216
#define BIASOFF 13824
#define SMEM_BYTES ((BIASOFF + 64) * 4)      // 55552

// ---------------------------------------------------------------------------
// TF32 GEMM: C[M, gridDim.x*64] = act(A[M,K] @ B[K,N] + bias)
// CTA tile 128x64, BK=32, 256 threads: 8 warps as 4(row)x2(col) of 32x32.
// 2-stage cp.async double buffer. A must be tf32-pre-rounded. K % 32 == 0.
// SCATTER: red.add.v2 into C[sidx[row]].  RSTORE: store tf32-rounded.
// zaux (optional, col0<256 blocks): zero zaux[r*ldc + col0 + ...] (aggr).
// dup (optional, non-scatter): also store result to dup[r*256 + c] (h copy).
// ---------------------------------------------------------------------------
template <bool RELU, bool SCATTER, bool RSTORE>
__global__ __launch_bounds__(256, 3) void tf32gemm(
    const float* __restrict__ A, int lda,
    const float* __restrict__ B, int ldb,
    const float* __restrict__ bias,
    float* __restrict__ C, int ldc,
    int M, int K,
    const int* __restrict__ sidx,
    float* __restrict__ zaux,
    float* __restrict__ dup)
{
    extern __shared__ unsigned dynsmem[];

    const int tid  = threadIdx.x;
    const int lane = tid & 31;
    const int wid  = tid >> 5;
    const int warpRow = wid >> 1;        // 0..3 (32 rows each)
    const int warpCol = wid & 1;         // 0..1 (32 cols each)
    const int qr = lane >> 2;            // 0..7
    const int qk = lane & 3;             // 0..3

    const int row0 = blockIdx.y * 128;
    const int col0 = blockIdx.x * 64;

    float* sbias = (float*)(dynsmem + BIASOFF);
    if (tid < 64) sbias[tid] = bias ? bias[col0 + tid] : 0.f;

    const int nc = K >> 5;

    auto cpA = [&](int s, int k0) {
        unsigned* buf = dynsmem + (s & 1) * ABUF;
#pragma unroll
        for (int i = 0; i < 4; i++) {
            int idx = tid + i * 256;        // 0..1023
            int row = idx >> 3;             // 0..127
            int c4  = idx & 7;              // 0..7
            int gr  = min(row0 + row, M - 1);
            cp16(smem_u32(&buf[row * AW + c4 * 4]),
                 A + (size_t)gr * lda + k0 + c4 * 4);
        }
    };
    auto cpB = [&](int s, int k0) {
        unsigned* buf = dynsmem + BOFF + (s & 1) * BBUF;
#pragma unroll
        for (int i = 0; i < 2; i++) {
            int idx = tid + i * 256;        // 0..511
            int k   = idx >> 4;             // 0..31
            int c4  = idx & 15;             // 0..15
            cp16(smem_u32(&buf[k * BW + c4 * 4]),
                 B + (size_t)(k0 + k) * ldb + col0 + c4 * 4);
        }
    };

    cpA(0, 0);  cpB(0, 0);  cp_commit();
    if (nc > 1) { cpA(1, 32); cpB(1, 32); cp_commit(); }

    float acc[2][4][4];
#pragma unroll
    for (int i = 0; i < 2; i++)
#pragma unroll
        for (int j = 0; j < 4; j++)
#pragma unroll
            for (int c = 0; c < 4; c++) acc[i][j][c] = 0.f;

    const int mbase = warpRow * 32;
    const int nbase = warpCol * 32;

    for (int s = 0; s < nc; s++) {
        if (s + 1 < nc)
            asm volatile("cp.async.wait_group 1;" ::: "memory");
        else
            asm volatile("cp.async.wait_group 0;" ::: "memory");
        __syncthreads();

        const unsigned* As = dynsmem + (s & 1) * ABUF;
        const unsigned* Bs = dynsmem + BOFF + (s & 1) * BBUF;

#pragma unroll
        for (int kk = 0; kk < 32; kk += 8) {
            unsigned a[2][4], b[4][2];
#pragma unroll
            for (int i = 0; i < 2; i++) {
                int r = mbase + i * 16 + qr;
                a[i][0] = As[r * AW + kk + qk];
                a[i][1] = As[(r + 8) * AW + kk + qk];
                a[i][2] = As[r * AW + kk + 4 + qk];
                a[i][3] = As[(r + 8) * AW + kk + 4 + qk];
            }
#pragma unroll
            for (int j = 0; j < 4; j++) {
                int c = nbase + j * 8 + qr;
                b[j][0] = Bs[(kk + qk) * BW + c];
                b[j][1] = Bs[(kk + 4 + qk) * BW + c];
            }
#pragma unroll
            for (int i = 0; i < 2; i++)
#pragma unroll
                for (int j = 0; j < 4; j++) {
                    asm volatile(
                        "mma.sync.aligned.m16n8k8.row.col.f32.tf32.tf32.f32 "
                        "{%0,%1,%2,%3}, {%4,%5,%6,%7}, {%8,%9}, {%0,%1,%2,%3};"
                        : "+f"(acc[i][j][0]), "+f"(acc[i][j][1]),
                          "+f"(acc[i][j][2]), "+f"(acc[i][j][3])
                        : "r"(a[i][0]), "r"(a[i][1]), "r"(a[i][2]), "r"(a[i][3]),
                          "r"(b[j][0]), "r"(b[j][1]));
                }
        }

        __syncthreads();          // all warps done with buf s before overwrite
        if (s + 2 < nc) {
            cpA(s + 2, (s + 2) << 5);
            cpB(s + 2, (s + 2) << 5);
            cp_commit();
        }
    }

    // ---- epilogue ----
#pragma unroll
    for (int i = 0; i < 2; i++) {
#pragma unroll
        for (int h = 0; h < 2; h++) {
            int r = row0 + mbase + i * 16 + qr + h * 8;
            if (r >= M) continue;
            if (SCATTER) {
                int target = sidx[r];
                float* Crow = C + (size_t)target * ldc;
#pragma unroll
                for (int j = 0; j < 4; j++) {
                    int c = col0 + nbase + j * 8 + 2 * qk;
                    float v0 = acc[i][j][h * 2 + 0] + sbias[c - col0];
                    float v1 = acc[i][j][h * 2 + 1] + sbias[c - col0 + 1];
                    if (RELU) { v0 = fmaxf(v0, 0.f); v1 = fmaxf(v1, 0.f); }
                    asm volatile("red.global.add.v2.f32 [%0], {%1, %2};"
                                 :: "l"(Crow + c), "f"(v0), "f"(v1) : "memory");
                }
            } else {
                float* Crow = C + (size_t)r * ldc;
#pragma unroll
                for (int j = 0; j < 4; j++) {
                    int c = col0 + nbase + j * 8 + 2 * qk;
                    float v0 = acc[i][j][h * 2 + 0] + sbias[c - col0];
                    float v1 = acc[i][j][h * 2 + 1] + sbias[c - col0 + 1];
                    if (RELU) { v0 = fmaxf(v0, 0.f); v1 = fmaxf(v1, 0.f); }
                    if (RSTORE) { v0 = f2tf_f(v0); v1 = f2tf_f(v1); }
                    *(float2*)(Crow + c) = make_float2(v0, v1);
                    if (dup != nullptr)
                        *(float2*)(dup + (size_t)r * 256 + c) = make_float2(v0, v1);
                }
                if (zaux != nullptr && col0 < 256) {
                    float* Zrow = zaux + (size_t)r * ldc;
#pragma unroll
                    for (int j = 0; j < 4; j++) {
                        int c = col0 + nbase + j * 8 + 2 * qk;
                        *(float2*)(Zrow + c) = make_float2(0.f, 0.f);
                    }
                }
            }
        }
    }
}

// ---------------------------------------------------------------------------
// One-shot preamble: tf32-round all weights + x; repack msg_w1[0:512] into
// Wab[256][512].
// ---------------------------------------------------------------------------
__global__ __launch_bounds__(256) void cvt_all(
    const float* __restrict__ msg_w1, const float* __restrict__ msg_w2,
    const float* __restrict__ up_w1,  const float* __restrict__ up_w2,
    const float* __restrict__ node_w, const float* __restrict__ tok_w1,
    const float* __restrict__ x,
    float* __restrict__ Wc, float* __restrict__ Xc)
{
    const int b = blockIdx.x;
    const int t = threadIdx.x;
    const float* src;
    float* dst;
    int i4;
    if (b < 384) {                       // repack Wab: 3*256*512/4 f4
        i4 = b * 256 + t;
        int l   = i4 >> 15;
        int rem = i4 & 32767;
        int k   = rem >> 7;
        int n   = (rem & 127) << 2;
        src = (n < 256)
            ? msg_w1 + (size_t)l * 544 * 256 + (size_t)k * 256 + n
            : msg_w1 + (size_t)l * 544 * 256 + (size_t)(256 + k) * 256 + (n - 256);
        dst = Wc + WC_MSGAB + (size_t)i4 * 4;
    } else if (b < 576) {
        i4 = (b - 384) * 256 + t;
        src = msg_w2 + (size_t)i4 * 4; dst = Wc + WC_MSG2 + (size_t)i4 * 4;
    } else if (b < 960) {
        i4 = (b - 576) * 256 + t;
        src = up_w1 + (size_t)i4 * 4;  dst = Wc + WC_UP1 + (size_t)i4 * 4;
    } else if (b < 1152) {
        i4 = (b - 960) * 256 + t;
        src = up_w2 + (size_t)i4 * 4;  dst = Wc + WC_UP2 + (size_t)i4 * 4;
    } else if (b < 1184) {
        i4 = (b - 1152) * 256 + t;
        src = node_w + (size_t)i4 * 4; dst = Wc + WC_NODE + (size_t)i4 * 4;
    } else if (b < 1216) {
        i4 = (b - 1184) * 256 + t;
        src = tok_w1 + (size_t)i4 * 4; dst = Wc + WC_TOK + (size_t)i4 * 4;
    } else {
        i4 = (b - 1216) * 256 + t;
        src = x + (size_t)i4 * 4;      dst = Xc + (size_t)i4 * 4;
    }
    float4 v = *(const float4*)src;
    float4 o = { f2tf_f(v.x), f2tf_f(v.y), f2tf_f(v.z), f2tf_f(v.w) };
    *(float4*)dst = o;
}
#define CVT_ALL_BLOCKS (1216 + 6250)

// round aggr half of Hcat in place (post-scatter, pre-up1)
__global__ void cvt_aggr(float* __restrict__ Hcat, int N)
{
    int idx = blockIdx.x * blockDim.x + threadIdx.x;
    if (idx < N * 64) {
        int r = idx >> 6, c = (idx & 63) << 2;
        float4* p = (float4*)(Hcat + (size_t)r * 512 + 256 + c);
        float4 v = *p;
        float4 o = { f2tf_f(v.x), f2tf_f(v.y), f2tf_f(v.z), f2tf_f(v.w) };
        *p = o;
    }
}

// ---------------------------------------------------------------------------
// hidden1[e, :] = rna(relu( Pa[dst[e]] + Pb[src[e]] + ebuf[e]·Wc + b1 ))
// ET=32 edges/block, edge loop 2x unrolled (two independent chains).
// ---------------------------------------------------------------------------
#define ET 32
__global__ __launch_bounds__(256) void hidden1_kernel(
    const float* __restrict__ P,
    const float* __restrict__ Ebuf,
    const float* __restrict__ Wc,
    const float* __restrict__ b1,
    const int* __restrict__ src,
    const int* __restrict__ dst,
    float* __restrict__ out,
    int E)
{
    const int j = threadIdx.x;
    const int e0 = blockIdx.x * ET;
    __shared__ float esm[ET][32];
    __shared__ int sdst[ET], ssrc[ET];

    float wc[32];
#pragma unroll
    for (int k = 0; k < 32; k++) wc[k] = Wc[k * 256 + j];

    const int ne = min(ET, E - e0);
    if (j < ne) sdst[j] = dst[e0 + j];
    else if (j >= 64 && j < 64 + ne) ssrc[j - 64] = src[e0 + (j - 64)];
    for (int t = j; t < ne * 32; t += 256)
        esm[t >> 5][t & 31] = Ebuf[(size_t)e0 * 32 + t];
    __syncthreads();

    const float bj = b1[j];
    for (int i = 0; i < ne; i += 2) {
        float acc0 = bj + P[(size_t)sdst[i] * 512 + j]
                        + P[(size_t)ssrc[i] * 512 + 256 + j];
        float acc1 = 0.f;
        const bool two = (i + 1 < ne);
        if (two)
            acc1 = bj + P[(size_t)sdst[i + 1] * 512 + j]
                      + P[(size_t)ssrc[i + 1] * 512 + 256 + j];
#pragma unroll
        for (int k = 0; k < 32; k++) {
            acc0 = fmaf(esm[i][k], wc[k], acc0);
            if (two) acc1 = fmaf(esm[i + 1][k], wc[k], acc1);
        }
        out[(size_t)(e0 + i) * 256 + j] = f2tf_f(fmaxf(acc0, 0.f));
        if (two)
            out[(size_t)(e0 + i + 1) * 256 + j] = f2tf_f(fmaxf(acc1, 0.f));
    }
}

// ---------------------------------------------------------------------------
__global__ __launch_bounds__(256) void edge_proj(
    const float* __restrict__ ea, const float* __restrict__ W,
    const float* __restrict__ b, float* __restrict__ out, int E)
{
    __shared__ float Ws[1024];
    __shared__ float es[8][32];
    const int t = threadIdx.x;
    for (int i = t; i < 1024; i += 256) Ws[i] = W[i];
    const int e0 = blockIdx.x * 8;
    const int ne = min(8, E - e0);
    for (int i = t; i < ne * 32; i += 256)
        es[i >> 5][i & 31] = ea[(size_t)e0 * 32 + i];
    __syncthreads();
    const int el = t >> 5, c = t & 31;
    if (el < ne) {
        float acc = b[c];
#pragma unroll
        for (int k = 0; k < 32; k++) acc = fmaf(es[el][k], Ws[k * 32 + c], acc);
        out[(size_t)(e0 + el) * 32 + c] = acc;
    }
}

__global__ void head2(const float* __restrict__ T, const float* __restrict__ w2,
                      const float* __restrict__ b2, float* __restrict__ out, int N)
{
    int gw = (blockIdx.x * blockDim.x + threadIdx.x) >> 5;
    int lane = threadIdx.x & 31;
    if (gw >= N) return;
    const float* row = T + (size_t)gw * 128;
    float s = 0.f;
#pragma unroll
    for (int k = lane; k < 128; k += 32) s = fmaf(row[k], w2[k], s);
#pragma unroll
    for (int o = 16; o; o >>= 1) s += __shfl_xor_sync(0xFFFFFFFFu, s, o);
    if (lane == 0) out[gw] = s + b2[0];
}

// ---------------------------------------------------------------------------
extern "C" void kernel_launch(void* const* d_in, const int* in_sizes, int n_in,
                              void* d_out, int out_size)
{
    const float* x       = (const float*)d_in[0];
    const int*   ei      = (const int*)d_in[1];
    const float* ea      = (const float*)d_in[2];
    const float* node_w  = (const float*)d_in[3];
    const float* node_b  = (const float*)d_in[4];
    const float* edge_w  = (const float*)d_in[5];
    const float* edge_b  = (const float*)d_in[6];
    const float* msg_w1  = (const float*)d_in[7];
    const float* msg_b1  = (const float*)d_in[8];
    const float* msg_w2  = (const float*)d_in[9];
    const float* msg_b2  = (const float*)d_in[10];
    const float* up_w1   = (const float*)d_in[11];
    const float* up_b1   = (const float*)d_in[12];
    const float* up_w2   = (const float*)d_in[13];
    const float* up_b2   = (const float*)d_in[14];
    const float* tok_w1  = (const float*)d_in[15];
    const float* tok_b1  = (const float*)d_in[16];
    const float* tok_w2  = (const float*)d_in[17];
    const float* tok_b2  = (const float*)d_in[18];

    const int N = in_sizes[0] / 128;   // 50000
    const int E = in_sizes[2] / 32;    // 400000
    const int* src = ei;
    const int* dst = ei + E;

    float *Hcat, *P, *M1, *U, *Eb, *T, *Xc, *Wc;
    cudaGetSymbolAddress((void**)&Hcat, g_Hcat);
    cudaGetSymbolAddress((void**)&P,    g_P);
    cudaGetSymbolAddress((void**)&M1,   g_M1);
    cudaGetSymbolAddress((void**)&U,    g_U);
    cudaGetSymbolAddress((void**)&Eb,   g_E);
    cudaGetSymbolAddress((void**)&T,    g_T);
    cudaGetSymbolAddress((void**)&Xc,   g_Xc);
    cudaGetSymbolAddress((void**)&Wc,   g_Wc);

    float* out_logits = (float*)d_out;
    float* out_h      = out_logits + N;

    const int mbN = (N + 127) / 128;   // 391
    const int mbE = (E + 127) / 128;   // 3125

    // ALL five instantiations used below must get the smem opt-in.
    cudaFuncSetAttribute(tf32gemm<false, false, true >, cudaFuncAttributeMaxDynamicSharedMemorySize, SMEM_BYTES);
    cudaFuncSetAttribute(tf32gemm<false, false, false>, cudaFuncAttributeMaxDynamicSharedMemorySize, SMEM_BYTES);
    cudaFuncSetAttribute(tf32gemm<true,  true,  false>, cudaFuncAttributeMaxDynamicSharedMemorySize, SMEM_BYTES);
    cudaFuncSetAttribute(tf32gemm<true,  false, true >, cudaFuncAttributeMaxDynamicSharedMemorySize, SMEM_BYTES);
    cudaFuncSetAttribute(tf32gemm<true,  false, false>, cudaFuncAttributeMaxDynamicSharedMemorySize, SMEM_BYTES);

    // ---- preamble: convert/repack all weights + x ----
    cvt_all<<<CVT_ALL_BLOCKS, 256>>>(msg_w1, msg_w2, up_w1, up_w2,
                                     node_w, tok_w1, x, Wc, Xc);

    // h = x @ node_w + node_b -> Hcat[:, 0:256] (stored rounded)
    tf32gemm<false, false, true><<<dim3(4, mbN), 256, SMEM_BYTES>>>(
        Xc, 128, Wc + WC_NODE, 256, node_b, Hcat, 512, N, 128,
        nullptr, nullptr, nullptr);
    // e = edge_attr @ edge_w + edge_b
    edge_proj<<<(E + 7) / 8, 256>>>(ea, edge_w, edge_b, Eb, E);

    for (int l = 0; l < 3; l++) {
        // [Pa | Pb] = h @ Wab; col0<256 blocks also zero the aggr half
        tf32gemm<false, false, false><<<dim3(8, mbN), 256, SMEM_BYTES>>>(
            Hcat, 512, Wc + WC_MSGAB + (size_t)l * 256 * 512, 512,
            nullptr, P, 512, N, 256, nullptr, Hcat + 256, nullptr);
        // hidden1 = rna(relu(Pa[dst] + Pb[src] + e@Wc + b1)) -> M1
        hidden1_kernel<<<(E + ET - 1) / ET, 256>>>(
            P, Eb, msg_w1 + (size_t)l * 544 * 256 + 512 * 256,
            msg_b1 + l * 256, src, dst, M1, E);
        // m = relu(M1 @ W2 + b2); aggr[dst] += m  (fused scatter)
        tf32gemm<true, true, false><<<dim3(4, mbE), 256, SMEM_BYTES>>>(
            M1, 256, Wc + WC_MSG2 + (size_t)l * 256 * 256, 256,
            msg_b2 + l * 256, Hcat + 256, 512, E, 256, dst, nullptr, nullptr);
        // round aggr in place (same rna the old cvt-staging applied)
        cvt_aggr<<<(N * 64 + 255) / 256, 256>>>(Hcat, N);
        // u = relu([h|aggr] @ up_w1 + b1)
        tf32gemm<true, false, true><<<dim3(4, mbN), 256, SMEM_BYTES>>>(
            Hcat, 512, Wc + WC_UP1 + (size_t)l * 512 * 256, 256,
            up_b1 + l * 256, U, 256, N, 512, nullptr, nullptr, nullptr);
        // h = relu(u @ up_w2 + b2) -> Hcat[:, 0:256]; last layer also -> out_h
        tf32gemm<true, false, true><<<dim3(4, mbN), 256, SMEM_BYTES>>>(
            U, 256, Wc + WC_UP2 + (size_t)l * 256 * 256, 256,
            up_b2 + l * 256, Hcat, 512, N, 256, nullptr, nullptr,
            (l == 2) ? out_h : nullptr);
    }

    // token head
    tf32gemm<true, false, false><<<dim3(2, mbN), 256, SMEM_BYTES>>>(
        Hcat, 512, Wc + WC_TOK, 128, tok_b1, T, 128, N, 256,
        nullptr, nullptr, nullptr);
    head2<<<(N * 32 + 255) / 256, 256>>>(T, tok_w2, tok_b2, out_logits, N);
}

// round 14
// speedup vs baseline: 1.3735x; 1.3735x over previous
#include <cuda_runtime.h>
#include <cuda_fp16.h>
#include <cstdint>

// ---------------------------------------------------------------------------
// GNN message passing, 50000 nodes / 400000 edges / HIDDEN=256 / 3 layers.
// R14: GEMMs moved from tf32 m16n8k8 to fp16 mma.sync.m16n8k16 (fp32 accum).
// fp16 and tf32 have the SAME 11-bit significand (same input rounding error),
// but 2x tensor throughput and half the fragment/staging smem bytes — the two
// resources proven binding in R10-R13. Structure = R12 best config:
// CTA 128x128, warp 32x64, BK=32, 3-stage cp.async, 2 CTA/SM.
// Weights pre-packed K-pair-interleaved half2 ([K/2][N] words) in preamble;
// activations stored plain half (pairs naturally contiguous).
// PaPb merged (N=512); aggr zeroing folded into PaPb epilogue (fp32 g_Aggr);
// scatter fused into edge GEMM epilogue (red.global.add.v2.f32);
// hidden1 ET=32 2x-unrolled; copy_h folded into last up2 (dup store).
// ---------------------------------------------------------------------------

#define NN 50000
#define NE 400000

__device__ __half g_Hcat[(size_t)NN * 512];  // [h | aggr] halves
__device__ float  g_Aggr[(size_t)NN * 256];  // fp32 scatter accumulator
__device__ float  g_P[(size_t)NN * 512];     // [Pa | Pb] fp32
__device__ __half g_M1[(size_t)NE * 256];    // hidden1 per edge (half)
__device__ __half g_U[(size_t)NN * 256];     // update hidden (half)
__device__ float  g_E[(size_t)NE * 32];      // projected edge features
__device__ float  g_T[(size_t)NN * 128];     // token head hidden (fp32)
__device__ __half g_Xh[(size_t)NN * 128];    // x (half)
__device__ unsigned g_Wh[622592];            // weights, packed half2 words

// g_Wh offsets (uint32 words)
#define WH_MSGAB 0                           // 3*128*512
#define WH_MSG2  196608                      // 3*128*256
#define WH_UP1   294912                      // 3*256*256
#define WH_UP2   491520                      // 3*128*256
#define WH_NODE  589824                      // 64*256
#define WH_TOK   606208                      // 128*128

__device__ __forceinline__ uint32_t smem_u32(const void* p) {
    return (uint32_t)__cvta_generic_to_shared(p);
}
__device__ __forceinline__ void cp16(uint32_t dst, const void* src) {
    asm volatile("cp.async.cg.shared.global [%0], [%1], 16;" :: "r"(dst), "l"(src));
}
__device__ __forceinline__ void cp_commit() {
    asm volatile("cp.async.commit_group;" ::: "memory");
}

// smem (words): A bufs 3*2560 @0 (128 rows x 20), B bufs 3*2176 @7680
// (16 kp x 136), bias 128 @14208
#define AW 20
#define ABUF 2560
#define BW 136
#define BBUF 2176
#define BOFF 7680
#define BIASOFF 14208
#define SMEM_BYTES ((BIASOFF + 128) * 4)     // 57344

// ---------------------------------------------------------------------------
// FP16 GEMM: C[M, gridDim.x*128] = act(A[M,K] @ B[K,N] + bias), fp32 accum.
// A: __half row-major (lda halves). B: packed half2 words [K/2][ldb words].
// 128x128 CTA, warp 32x64, BK=32 (2 x m16n8k16 blocks), 3-stage cp.async.
// SCATTER: red.add.v2 fp32 into Cf[sidx[row]*ldc + c].
// RSTORE: store half into Ch[r*ldc + c]; else fp32 into Cf.
// zaux (col0<256 blocks): zero zaux[r*256 + c] (fp32 aggr).
// dup: also store fp32 copy of (half-rounded) result to dup[r*256 + c].
// ---------------------------------------------------------------------------
template <bool RELU, bool SCATTER, bool RSTORE>
__global__ __launch_bounds__(256, 2) void h16gemm(
    const __half* __restrict__ A, int lda,
    const unsigned* __restrict__ B, int ldb,
    const float* __restrict__ bias,
    float* __restrict__ Cf, __half* __restrict__ Ch, int ldc,
    int M, int K,
    const int* __restrict__ sidx,
    float* __restrict__ zaux,
    float* __restrict__ dup)
{
    extern __shared__ unsigned dynsmem[];

    const int tid  = threadIdx.x;
    const int lane = tid & 31;
    const int wid  = tid >> 5;
    const int warpRow = wid >> 1;        // 0..3 (32 rows)
    const int warpCol = wid & 1;         // 0..1 (64 cols)
    const int qr = lane >> 2;
    const int qk = lane & 3;

    const int row0 = blockIdx.y * 128;
    const int col0 = blockIdx.x * 128;

    float* sbias = (float*)(dynsmem + BIASOFF);
    if (tid < 128) sbias[tid] = bias ? bias[col0 + tid] : 0.f;

    const int nc = K >> 5;               // chunks of 32 halves

    auto cpA = [&](int s, int k0) {      // 128 rows x 32 halves = 512 x 16B
        unsigned* buf = dynsmem + (s % 3) * ABUF;
#pragma unroll
        for (int i = 0; i < 2; i++) {
            int idx = tid + i * 256;     // 0..511
            int row = idx >> 2;          // 0..127
            int c16 = idx & 3;           // 0..3 (16B units)
            int gr  = min(row0 + row, M - 1);
            cp16(smem_u32(&buf[row * AW + c16 * 4]),
                 A + (size_t)gr * lda + k0 + c16 * 8);
        }
    };
    auto cpB = [&](int s, int k0) {      // 16 kp x 128 words = 512 x 16B
        unsigned* buf = dynsmem + BOFF + (s % 3) * BBUF;
        int kp0 = k0 >> 1;
#pragma unroll
        for (int i = 0; i < 2; i++) {
            int idx = tid + i * 256;     // 0..511
            int kp  = idx >> 5;          // 0..15
            int c4  = idx & 31;          // 0..31
            cp16(smem_u32(&buf[kp * BW + c4 * 4]),
                 B + (size_t)(kp0 + kp) * ldb + col0 + c4 * 4);
        }
    };

    cpA(0, 0);  cpB(0, 0);  cp_commit();
    if (nc > 1) { cpA(1, 32); cpB(1, 32); cp_commit(); }

    float acc[2][8][4];
#pragma unroll
    for (int i = 0; i < 2; i++)
#pragma unroll
        for (int j = 0; j < 8; j++)
#pragma unroll
            for (int c = 0; c < 4; c++) acc[i][j][c] = 0.f;

    const int mbase = warpRow * 32;
    const int nbase = warpCol * 64;

    for (int s = 0; s < nc; s++) {
        if (s + 1 < nc)
            asm volatile("cp.async.wait_group 1;" ::: "memory");
        else
            asm volatile("cp.async.wait_group 0;" ::: "memory");
        __syncthreads();

        if (s + 2 < nc) {
            cpA(s + 2, (s + 2) << 5);
            cpB(s + 2, (s + 2) << 5);
            cp_commit();
        }

        const unsigned* As = dynsmem + (s % 3) * ABUF;
        const unsigned* Bs = dynsmem + BOFF + (s % 3) * BBUF;

#pragma unroll
        for (int b16 = 0; b16 < 2; b16++) {   // two m16n8k16 K-blocks
            const int p0 = b16 * 8;
            unsigned a[2][4], b[8][2];
#pragma unroll
            for (int i = 0; i < 2; i++) {
                int r = mbase + i * 16 + qr;
                a[i][0] = As[r * AW + p0 + qk];
                a[i][1] = As[(r + 8) * AW + p0 + qk];
                a[i][2] = As[r * AW + p0 + qk + 4];
                a[i][3] = As[(r + 8) * AW + p0 + qk + 4];
            }
#pragma unroll
            for (int j = 0; j < 8; j++) {
                int c = nbase + j * 8 + qr;
                b[j][0] = Bs[(p0 + qk) * BW + c];
                b[j][1] = Bs[(p0 + qk + 4) * BW + c];
            }
#pragma unroll
            for (int i = 0; i < 2; i++)
#pragma unroll
                for (int j = 0; j < 8; j++) {
                    asm volatile(
                        "mma.sync.aligned.m16n8k16.row.col.f32.f16.f16.f32 "
                        "{%0,%1,%2,%3}, {%4,%5,%6,%7}, {%8,%9}, {%0,%1,%2,%3};"
                        : "+f"(acc[i][j][0]), "+f"(acc[i][j][1]),
                          "+f"(acc[i][j][2]), "+f"(acc[i][j][3])
                        : "r"(a[i][0]), "r"(a[i][1]), "r"(a[i][2]), "r"(a[i][3]),
                          "r"(b[j][0]), "r"(b[j][1]));
                }
        }
    }

    // ---- epilogue ----
#pragma unroll
    for (int i = 0; i < 2; i++) {
#pragma unroll
        for (int h = 0; h < 2; h++) {
            int r = row0 + mbase + i * 16 + qr + h * 8;
            if (r >= M) continue;
            if (SCATTER) {
                int target = sidx[r];
                float* Crow = Cf + (size_t)target * ldc;
#pragma unroll
                for (int j = 0; j < 8; j++) {
                    int c = col0 + nbase + j * 8 + 2 * qk;
                    float v0 = acc[i][j][h * 2 + 0] + sbias[c - col0];
                    float v1 = acc[i][j][h * 2 + 1] + sbias[c - col0 + 1];
                    if (RELU) { v0 = fmaxf(v0, 0.f); v1 = fmaxf(v1, 0.f); }
                    asm volatile("red.global.add.v2.f32 [%0], {%1, %2};"
                                 :: "l"(Crow + c), "f"(v0), "f"(v1) : "memory");
                }
            } else {
#pragma unroll
                for (int j = 0; j < 8; j++) {
                    int c = col0 + nbase + j * 8 + 2 * qk;
                    float v0 = acc[i][j][h * 2 + 0] + sbias[c - col0];
                    float v1 = acc[i][j][h * 2 + 1] + sbias[c - col0 + 1];
                    if (RELU) { v0 = fmaxf(v0, 0.f); v1 = fmaxf(v1, 0.f); }
                    if (RSTORE) {
                        __half h0 = __float2half_rn(v0);
                        __half h1 = __float2half_rn(v1);
                        *(__half2*)(Ch + (size_t)r * ldc + c) =
                            __halves2half2(h0, h1);
                        if (dup != nullptr)
                            *(float2*)(dup + (size_t)r * 256 + c) =
                                make_float2(__half2float(h0), __half2float(h1));
                    } else {
                        *(float2*)(Cf + (size_t)r * ldc + c) = make_float2(v0, v1);
                    }
                }
                if (zaux != nullptr && col0 < 256) {
                    float* Zrow = zaux + (size_t)r * 256;
#pragma unroll
                    for (int j = 0; j < 8; j++) {
                        int c = col0 + nbase + j * 8 + 2 * qk;
                        *(float2*)(Zrow + c) = make_float2(0.f, 0.f);
                    }
                }
            }
        }
    }
}

// ---------------------------------------------------------------------------
// Preamble: convert weights to K-pair-interleaved half2 words + x to half.
// Each thread emits 4 words (2x float4 reads) for weights, or 8 halves for x.
// Block map: [0,192) Wab | [192,288) msg2 | [288,480) up1 | [480,576) up2 |
// [576,592) node | [592,608) tok | [608,3733) x.
// ---------------------------------------------------------------------------
__global__ __launch_bounds__(256) void cvt_all(
    const float* __restrict__ msg_w1, const float* __restrict__ msg_w2,
    const float* __restrict__ up_w1,  const float* __restrict__ up_w2,
    const float* __restrict__ node_w, const float* __restrict__ tok_w1,
    const float* __restrict__ x,
    unsigned* __restrict__ Wh, __half* __restrict__ Xh)
{
    const int b = blockIdx.x;
    const int t = threadIdx.x;

    if (b >= 608) {                      // x: 800000 groups of 8 halves
        int q = (b - 608) * 256 + t;
        float4 a = *(const float4*)(x + (size_t)q * 8);
        float4 c = *(const float4*)(x + (size_t)q * 8 + 4);
        __half2 h[4] = { __floats2half2_rn(a.x, a.y), __floats2half2_rn(a.z, a.w),
                         __floats2half2_rn(c.x, c.y), __floats2half2_rn(c.z, c.w) };
        *(uint4*)(Xh + (size_t)q * 8) = *(uint4*)h;
        return;
    }

    const float *r0, *r1;
    unsigned* dst;
    if (b < 192) {                       // Wab: 3 x [256][512], split msg_w1
        int q = b * 256 + t;             // < 49152
        int l   = q >> 14;
        int rem = q & 16383;
        int kp  = rem >> 7;
        int n0  = (rem & 127) << 2;
        const float* base = msg_w1 + (size_t)l * 544 * 256;
        int k0 = 2 * kp;
        if (n0 < 256) {
            r0 = base + (size_t)k0 * 256 + n0;
            r1 = base + (size_t)(k0 + 1) * 256 + n0;
        } else {
            r0 = base + (size_t)(256 + k0) * 256 + (n0 - 256);
            r1 = base + (size_t)(256 + k0 + 1) * 256 + (n0 - 256);
        }
        dst = Wh + WH_MSGAB + (size_t)((l * 128 + kp) * 512 + n0);
    } else if (b < 288) {                // msg_w2 flat [768][256]
        int q = (b - 192) * 256 + t;     // < 24576
        int kp = q >> 6, n0 = (q & 63) << 2;
        r0 = msg_w2 + (size_t)(2 * kp) * 256 + n0;
        r1 = msg_w2 + (size_t)(2 * kp + 1) * 256 + n0;
        dst = Wh + WH_MSG2 + (size_t)(kp * 256 + n0);
    } else if (b < 480) {                // up_w1 flat [1536][256]
        int q = (b - 288) * 256 + t;     // < 49152
        int kp = q >> 6, n0 = (q & 63) << 2;
        r0 = up_w1 + (size_t)(2 * kp) * 256 + n0;
        r1 = up_w1 + (size_t)(2 * kp + 1) * 256 + n0;
        dst = Wh + WH_UP1 + (size_t)(kp * 256 + n0);
    } else if (b < 576) {                // up_w2 flat [768][256]
        int q = (b - 480) * 256 + t;
        int kp = q >> 6, n0 = (q & 63) << 2;
        r0 = up_w2 + (size_t)(2 * kp) * 256 + n0;
        r1 = up_w2 + (size_t)(2 * kp + 1) * 256 + n0;
        dst = Wh + WH_UP2 + (size_t)(kp * 256 + n0);
    } else if (b < 592) {                // node_w [128][256]
        int q = (b - 576) * 256 + t;     // < 4096
        int kp = q >> 6, n0 = (q & 63) << 2;
        r0 = node_w + (size_t)(2 * kp) * 256 + n0;
        r1 = node_w + (size_t)(2 * kp + 1) * 256 + n0;
        dst = Wh + WH_NODE + (size_t)(kp * 256 + n0);
    } else {                             // tok_w1 [256][128]
        int q = (b - 592) * 256 + t;     // < 4096
        int kp = q >> 5, n0 = (q & 31) << 2;
        r0 = tok_w1 + (size_t)(2 * kp) * 128 + n0;
        r1 = tok_w1 + (size_t)(2 * kp + 1) * 128 + n0;
        dst = Wh + WH_TOK + (size_t)(kp * 128 + n0);
    }
    float4 a = *(const float4*)r0;
    float4 c = *(const float4*)r1;
    __half2 h0 = __floats2half2_rn(a.x, c.x);
    __half2 h1 = __floats2half2_rn(a.y, c.y);
    __half2 h2 = __floats2half2_rn(a.z, c.z);
    __half2 h3 = __floats2half2_rn(a.w, c.w);
    ((__half2*)dst)[0] = h0; ((__half2*)dst)[1] = h1;
    ((__half2*)dst)[2] = h2; ((__half2*)dst)[3] = h3;
}
#define CVT_ALL_BLOCKS 3733

// aggr fp32 -> half into Hcat[:, 256:512]
__global__ void cvt_aggr(const float* __restrict__ Aggr,
                         __half* __restrict__ Hcat, int N)
{
    int idx = blockIdx.x * blockDim.x + threadIdx.x;
    if (idx < N * 64) {
        int r = idx >> 6, c = (idx & 63) << 2;
        float4 v = *(const float4*)(Aggr + (size_t)r * 256 + c);
        __half2 h[2] = { __floats2half2_rn(v.x, v.y), __floats2half2_rn(v.z, v.w) };
        *(uint2*)(Hcat + (size_t)r * 512 + 256 + c) = *(uint2*)h;
    }
}

// ---------------------------------------------------------------------------
// hidden1[e, :] = half(relu( Pa[dst[e]] + Pb[src[e]] + ebuf[e]·Wc + b1 ))
// ET=32 edges/block, 2x unrolled.
// ---------------------------------------------------------------------------
#define ET 32
__global__ __launch_bounds__(256) void hidden1_kernel(
    const float* __restrict__ P,
    const float* __restrict__ Ebuf,
    const float* __restrict__ Wc,
    const float* __restrict__ b1,
    const int* __restrict__ src,
    const int* __restrict__ dst,
    __half* __restrict__ out,
    int E)
{
    const int j = threadIdx.x;
    const int e0 = blockIdx.x * ET;
    __shared__ float esm[ET][32];
    __shared__ int sdst[ET], ssrc[ET];

    float wc[32];
#pragma unroll
    for (int k = 0; k < 32; k++) wc[k] = Wc[k * 256 + j];

    const int ne = min(ET, E - e0);
    if (j < ne) sdst[j] = dst[e0 + j];
    else if (j >= 64 && j < 64 + ne) ssrc[j - 64] = src[e0 + (j - 64)];
    for (int t = j; t < ne * 32; t += 256)
        esm[t >> 5][t & 31] = Ebuf[(size_t)e0 * 32 + t];
    __syncthreads();

    const float bj = b1[j];
    for (int i = 0; i < ne; i += 2) {
        float acc0 = bj + P[(size_t)sdst[i] * 512 + j]
                        + P[(size_t)ssrc[i] * 512 + 256 + j];
        float acc1 = 0.f;
        const bool two = (i + 1 < ne);
        if (two)
            acc1 = bj + P[(size_t)sdst[i + 1] * 512 + j]
                      + P[(size_t)ssrc[i + 1] * 512 + 256 + j];
#pragma unroll
        for (int k = 0; k < 32; k++) {
            acc0 = fmaf(esm[i][k], wc[k], acc0);
            if (two) acc1 = fmaf(esm[i + 1][k], wc[k], acc1);
        }
        out[(size_t)(e0 + i) * 256 + j] = __float2half_rn(fmaxf(acc0, 0.f));
        if (two)
            out[(size_t)(e0 + i + 1) * 256 + j] = __float2half_rn(fmaxf(acc1, 0.f));
    }
}

// ---------------------------------------------------------------------------
__global__ __launch_bounds__(256) void edge_proj(
    const float* __restrict__ ea, const float* __restrict__ W,
    const float* __restrict__ b, float* __restrict__ out, int E)
{
    __shared__ float Ws[1024];
    __shared__ float es[8][32];
    const int t = threadIdx.x;
    for (int i = t; i < 1024; i += 256) Ws[i] = W[i];
    const int e0 = blockIdx.x * 8;
    const int ne = min(8, E - e0);
    for (int i = t; i < ne * 32; i += 256)
        es[i >> 5][i & 31] = ea[(size_t)e0 * 32 + i];
    __syncthreads();
    const int el = t >> 5, c = t & 31;
    if (el < ne) {
        float acc = b[c];
#pragma unroll
        for (int k = 0; k < 32; k++) acc = fmaf(es[el][k], Ws[k * 32 + c], acc);
        out[(size_t)(e0 + el) * 32 + c] = acc;
    }
}

__global__ void head2(const float* __restrict__ T, const float* __restrict__ w2,
                      const float* __restrict__ b2, float* __restrict__ out, int N)
{
    int gw = (blockIdx.x * blockDim.x + threadIdx.x) >> 5;
    int lane = threadIdx.x & 31;
    if (gw >= N) return;
    const float* row = T + (size_t)gw * 128;
    float s = 0.f;
#pragma unroll
    for (int k = lane; k < 128; k += 32) s = fmaf(row[k], w2[k], s);
#pragma unroll
    for (int o = 16; o; o >>= 1) s += __shfl_xor_sync(0xFFFFFFFFu, s, o);
    if (lane == 0) out[gw] = s + b2[0];
}

// ---------------------------------------------------------------------------
extern "C" void kernel_launch(void* const* d_in, const int* in_sizes, int n_in,
                              void* d_out, int out_size)
{
    const float* x       = (const float*)d_in[0];
    const int*   ei      = (const int*)d_in[1];
    const float* ea      = (const float*)d_in[2];
    const float* node_w  = (const float*)d_in[3];
    const float* node_b  = (const float*)d_in[4];
    const float* edge_w  = (const float*)d_in[5];
    const float* edge_b  = (const float*)d_in[6];
    const float* msg_w1  = (const float*)d_in[7];
    const float* msg_b1  = (const float*)d_in[8];
    const float* msg_w2  = (const float*)d_in[9];
    const float* msg_b2  = (const float*)d_in[10];
    const float* up_w1   = (const float*)d_in[11];
    const float* up_b1   = (const float*)d_in[12];
    const float* up_w2   = (const float*)d_in[13];
    const float* up_b2   = (const float*)d_in[14];
    const float* tok_w1  = (const float*)d_in[15];
    const float* tok_b1  = (const float*)d_in[16];
    const float* tok_w2  = (const float*)d_in[17];
    const float* tok_b2  = (const float*)d_in[18];

    const int N = in_sizes[0] / 128;   // 50000
    const int E = in_sizes[2] / 32;    // 400000
    const int* src = ei;
    const int* dst = ei + E;

    __half *Hcat, *M1, *U, *Xh;
    float *Aggr, *P, *Eb, *T;
    unsigned* Wh;
    cudaGetSymbolAddress((void**)&Hcat, g_Hcat);
    cudaGetSymbolAddress((void**)&Aggr, g_Aggr);
    cudaGetSymbolAddress((void**)&P,    g_P);
    cudaGetSymbolAddress((void**)&M1,   g_M1);
    cudaGetSymbolAddress((void**)&U,    g_U);
    cudaGetSymbolAddress((void**)&Eb,   g_E);
    cudaGetSymbolAddress((void**)&T,    g_T);
    cudaGetSymbolAddress((void**)&Xh,   g_Xh);
    cudaGetSymbolAddress((void**)&Wh,   g_Wh);

    float* out_logits = (float*)d_out;
    float* out_h      = out_logits + N;

    const int mbN = (N + 127) / 128;   // 391
    const int mbE = (E + 127) / 128;   // 3125

    // ALL five instantiations used below must get the smem opt-in.
    cudaFuncSetAttribute(h16gemm<false, false, true >, cudaFuncAttributeMaxDynamicSharedMemorySize, SMEM_BYTES);
    cudaFuncSetAttribute(h16gemm<false, false, false>, cudaFuncAttributeMaxDynamicSharedMemorySize, SMEM_BYTES);
    cudaFuncSetAttribute(h16gemm<true,  true,  false>, cudaFuncAttributeMaxDynamicSharedMemorySize, SMEM_BYTES);
    cudaFuncSetAttribute(h16gemm<true,  false, true >, cudaFuncAttributeMaxDynamicSharedMemorySize, SMEM_BYTES);
    cudaFuncSetAttribute(h16gemm<true,  false, false>, cudaFuncAttributeMaxDynamicSharedMemorySize, SMEM_BYTES);

    // ---- preamble: pack weights (K-pair half2) + convert x ----
    cvt_all<<<CVT_ALL_BLOCKS, 256>>>(msg_w1, msg_w2, up_w1, up_w2,
                                     node_w, tok_w1, x, Wh, Xh);

    // h = x @ node_w + node_b -> Hcat[:, 0:256] (half)
    h16gemm<false, false, true><<<dim3(2, mbN), 256, SMEM_BYTES>>>(
        Xh, 128, Wh + WH_NODE, 256, node_b, nullptr, Hcat, 512, N, 128,
        nullptr, nullptr, nullptr);
    // e = edge_attr @ edge_w + edge_b
    edge_proj<<<(E + 7) / 8, 256>>>(ea, edge_w, edge_b, Eb, E);

    for (int l = 0; l < 3; l++) {
        // [Pa | Pb] = h @ Wab (fp32 out); col0<256 blocks zero g_Aggr
        h16gemm<false, false, false><<<dim3(4, mbN), 256, SMEM_BYTES>>>(
            Hcat, 512, Wh + WH_MSGAB + (size_t)l * 65536, 512,
            nullptr, P, nullptr, 512, N, 256, nullptr, Aggr, nullptr);
        // hidden1 = half(relu(Pa[dst] + Pb[src] + e@Wc + b1)) -> M1
        hidden1_kernel<<<(E + ET - 1) / ET, 256>>>(
            P, Eb, msg_w1 + (size_t)l * 544 * 256 + 512 * 256,
            msg_b1 + l * 256, src, dst, M1, E);
        // m = relu(M1 @ W2 + b2); Aggr[dst] += m  (fused scatter, fp32)
        h16gemm<true, true, false><<<dim3(2, mbE), 256, SMEM_BYTES>>>(
            M1, 256, Wh + WH_MSG2 + (size_t)l * 32768, 256,
            msg_b2 + l * 256, Aggr, nullptr, 256, E, 256, dst, nullptr, nullptr);
        // aggr fp32 -> half into Hcat[:, 256:512]
        cvt_aggr<<<(N * 64 + 255) / 256, 256>>>(Aggr, Hcat, N);
        // u = relu([h|aggr] @ up_w1 + b1) -> U (half)
        h16gemm<true, false, true><<<dim3(2, mbN), 256, SMEM_BYTES>>>(
            Hcat, 512, Wh + WH_UP1 + (size_t)l * 65536, 256,
            up_b1 + l * 256, nullptr, U, 256, N, 512, nullptr, nullptr, nullptr);
        // h = relu(u @ up_w2 + b2) -> Hcat[:, 0:256]; last layer also -> out_h
        h16gemm<true, false, true><<<dim3(2, mbN), 256, SMEM_BYTES>>>(
            U, 256, Wh + WH_UP2 + (size_t)l * 32768, 256,
            up_b2 + l * 256, nullptr, Hcat, 512, N, 256, nullptr, nullptr,
            (l == 2) ? out_h : nullptr);
    }

    // token head: T = relu(h @ tok_w1 + b1) (fp32 out)
    h16gemm<true, false, false><<<dim3(1, mbN), 256, SMEM_BYTES>>>(
        Hcat, 512, Wh + WH_TOK, 128, tok_b1, T, nullptr, 128, N, 256,
        nullptr, nullptr, nullptr);
    head2<<<(N * 32 + 255) / 256, 256>>>(T, tok_w2, tok_b2, out_logits, N);
}

// round 17
// speedup vs baseline: 1.4013x; 1.0202x over previous
#include <cuda_runtime.h>
#include <cuda_fp16.h>
#include <cstdint>

// ---------------------------------------------------------------------------
// GNN message passing, 50000 nodes / 400000 edges / HIDDEN=256 / 3 layers.
// fp16 mma.sync.m16n8k16 (fp32 accum) GEMMs; CTA 128x128, warp 32x64, BK=32,
// 3-stage cp.async, 2 CTA/SM. Weights pre-packed K-pair-interleaved half2.
// P ([Pa|Pb]) stored HALF — halves hidden1's gathered L2 traffic and PaPb's
// store traffic (R14 showed downstream roundings are noise vs the 11-bit
// input rounding: rel_err tf32 7.2291e-4 vs fp16 7.2255e-4).
// PaPb merged (N=512); aggr zeroing folded into PaPb epilogue (fp32 g_Aggr);
// scatter fused into edge GEMM epilogue (red.global.add.v2.f32);
// hidden1 ET=32 2x-unrolled; copy_h folded into last up2 (dup store).
// (R17 = third submission of this source; R15/R16 hit broker-level container
// failures with no kernel artifact — audited clean against passing R14.)
// ---------------------------------------------------------------------------

#define NN 50000
#define NE 400000

__device__ __half g_Hcat[(size_t)NN * 512];  // [h | aggr] halves
__device__ float  g_Aggr[(size_t)NN * 256];  // fp32 scatter accumulator
__device__ __half g_Ph[(size_t)NN * 512];    // [Pa | Pb] HALF
__device__ __half g_M1[(size_t)NE * 256];    // hidden1 per edge (half)
__device__ __half g_U[(size_t)NN * 256];     // update hidden (half)
__device__ float  g_E[(size_t)NE * 32];      // projected edge features
__device__ float  g_T[(size_t)NN * 128];     // token head hidden (fp32)
__device__ __half g_Xh[(size_t)NN * 128];    // x (half)
__device__ unsigned g_Wh[622592];            // weights, packed half2 words

// g_Wh offsets (uint32 words)
#define WH_MSGAB 0                           // 3*128*512
#define WH_MSG2  196608                      // 3*128*256
#define WH_UP1   294912                      // 3*256*256
#define WH_UP2   491520                      // 3*128*256
#define WH_NODE  589824                      // 64*256
#define WH_TOK   606208                      // 128*128

__device__ __forceinline__ uint32_t smem_u32(const void* p) {
    return (uint32_t)__cvta_generic_to_shared(p);
}
__device__ __forceinline__ void cp16(uint32_t dst, const void* src) {
    asm volatile("cp.async.cg.shared.global [%0], [%1], 16;" :: "r"(dst), "l"(src));
}
__device__ __forceinline__ void cp_commit() {
    asm volatile("cp.async.commit_group;" ::: "memory");
}

// smem (words): A bufs 3*2560 @0 (128 rows x 20), B bufs 3*2176 @7680
// (16 kp x 136), bias 128 @14208
#define AW 20
#define ABUF 2560
#define BW 136
#define BBUF 2176
#define BOFF 7680
#define BIASOFF 14208
#define SMEM_BYTES ((BIASOFF + 128) * 4)     // 57344

// ---------------------------------------------------------------------------
// FP16 GEMM: C[M, gridDim.x*128] = act(A[M,K] @ B[K,N] + bias), fp32 accum.
// A: __half row-major (lda halves). B: packed half2 words [K/2][ldb words].
// SCATTER: red.add.v2 fp32 into Cf[sidx[row]*ldc + c].
// RSTORE: store half into Ch[r*ldc + c]; else fp32 into Cf.
// zaux (col0<256 blocks): zero zaux[r*256 + c] (fp32 aggr).
// dup: also store fp32 copy of (half-rounded) result to dup[r*256 + c].
// ---------------------------------------------------------------------------
template <bool RELU, bool SCATTER, bool RSTORE>
__global__ __launch_bounds__(256, 2) void h16gemm(
    const __half* __restrict__ A, int lda,
    const unsigned* __restrict__ B, int ldb,
    const float* __restrict__ bias,
    float* __restrict__ Cf, __half* __restrict__ Ch, int ldc,
    int M, int K,
    const int* __restrict__ sidx,
    float* __restrict__ zaux,
    float* __restrict__ dup)
{
    extern __shared__ unsigned dynsmem[];

    const int tid  = threadIdx.x;
    const int lane = tid & 31;
    const int wid  = tid >> 5;
    const int warpRow = wid >> 1;        // 0..3 (32 rows)
    const int warpCol = wid & 1;         // 0..1 (64 cols)
    const int qr = lane >> 2;
    const int qk = lane & 3;

    const int row0 = blockIdx.y * 128;
    const int col0 = blockIdx.x * 128;

    float* sbias = (float*)(dynsmem + BIASOFF);
    if (tid < 128) sbias[tid] = bias ? bias[col0 + tid] : 0.f;

    const int nc = K >> 5;               // chunks of 32 halves

    auto cpA = [&](int s, int k0) {      // 128 rows x 32 halves = 512 x 16B
        unsigned* buf = dynsmem + (s % 3) * ABUF;
#pragma unroll
        for (int i = 0; i < 2; i++) {
            int idx = tid + i * 256;     // 0..511
            int row = idx >> 2;          // 0..127
            int c16 = idx & 3;           // 0..3 (16B units)
            int gr  = min(row0 + row, M - 1);
            cp16(smem_u32(&buf[row * AW + c16 * 4]),
                 A + (size_t)gr * lda + k0 + c16 * 8);
        }
    };
    auto cpB = [&](int s, int k0) {      // 16 kp x 128 words = 512 x 16B
        unsigned* buf = dynsmem + BOFF + (s % 3) * BBUF;
        int kp0 = k0 >> 1;
#pragma unroll
        for (int i = 0; i < 2; i++) {
            int idx = tid + i * 256;     // 0..511
            int kp  = idx >> 5;          // 0..15
            int c4  = idx & 31;          // 0..31
            cp16(smem_u32(&buf[kp * BW + c4 * 4]),
                 B + (size_t)(kp0 + kp) * ldb + col0 + c4 * 4);
        }
    };

    cpA(0, 0);  cpB(0, 0);  cp_commit();
    if (nc > 1) { cpA(1, 32); cpB(1, 32); cp_commit(); }

    float acc[2][8][4];
#pragma unroll
    for (int i = 0; i < 2; i++)
#pragma unroll
        for (int j = 0; j < 8; j++)
#pragma unroll
            for (int c = 0; c < 4; c++) acc[i][j][c] = 0.f;

    const int mbase = warpRow * 32;
    const int nbase = warpCol * 64;

    for (int s = 0; s < nc; s++) {
        if (s + 1 < nc)
            asm volatile("cp.async.wait_group 1;" ::: "memory");
        else
            asm volatile("cp.async.wait_group 0;" ::: "memory");
        __syncthreads();

        if (s + 2 < nc) {
            cpA(s + 2, (s + 2) << 5);
            cpB(s + 2, (s + 2) << 5);
            cp_commit();
        }

        const unsigned* As = dynsmem + (s % 3) * ABUF;
        const unsigned* Bs = dynsmem + BOFF + (s % 3) * BBUF;

#pragma unroll
        for (int b16 = 0; b16 < 2; b16++) {   // two m16n8k16 K-blocks
            const int p0 = b16 * 8;
            unsigned a[2][4], b[8][2];
#pragma unroll
            for (int i = 0; i < 2; i++) {
                int r = mbase + i * 16 + qr;
                a[i][0] = As[r * AW + p0 + qk];
                a[i][1] = As[(r + 8) * AW + p0 + qk];
                a[i][2] = As[r * AW + p0 + qk + 4];
                a[i][3] = As[(r + 8) * AW + p0 + qk + 4];
            }
#pragma unroll
            for (int j = 0; j < 8; j++) {
                int c = nbase + j * 8 + qr;
                b[j][0] = Bs[(p0 + qk) * BW + c];
                b[j][1] = Bs[(p0 + qk + 4) * BW + c];
            }
#pragma unroll
            for (int i = 0; i < 2; i++)
#pragma unroll
                for (int j = 0; j < 8; j++) {
                    asm volatile(
                        "mma.sync.aligned.m16n8k16.row.col.f32.f16.f16.f32 "
                        "{%0,%1,%2,%3}, {%4,%5,%6,%7}, {%8,%9}, {%0,%1,%2,%3};"
                        : "+f"(acc[i][j][0]), "+f"(acc[i][j][1]),
                          "+f"(acc[i][j][2]), "+f"(acc[i][j][3])
                        : "r"(a[i][0]), "r"(a[i][1]), "r"(a[i][2]), "r"(a[i][3]),
                          "r"(b[j][0]), "r"(b[j][1]));
                }
        }
    }

    // ---- epilogue ----
#pragma unroll
    for (int i = 0; i < 2; i++) {
#pragma unroll
        for (int h = 0; h < 2; h++) {
            int r = row0 + mbase + i * 16 + qr + h * 8;
            if (r >= M) continue;
            if (SCATTER) {
                int target = sidx[r];
                float* Crow = Cf + (size_t)target * ldc;
#pragma unroll
                for (int j = 0; j < 8; j++) {
                    int c = col0 + nbase + j * 8 + 2 * qk;
                    float v0 = acc[i][j][h * 2 + 0] + sbias[c - col0];
                    float v1 = acc[i][j][h * 2 + 1] + sbias[c - col0 + 1];
                    if (RELU) { v0 = fmaxf(v0, 0.f); v1 = fmaxf(v1, 0.f); }
                    asm volatile("red.global.add.v2.f32 [%0], {%1, %2};"
                                 :: "l"(Crow + c), "f"(v0), "f"(v1) : "memory");
                }
            } else {
#pragma unroll
                for (int j = 0; j < 8; j++) {
                    int c = col0 + nbase + j * 8 + 2 * qk;
                    float v0 = acc[i][j][h * 2 + 0] + sbias[c - col0];
                    float v1 = acc[i][j][h * 2 + 1] + sbias[c - col0 + 1];
                    if (RELU) { v0 = fmaxf(v0, 0.f); v1 = fmaxf(v1, 0.f); }
                    if (RSTORE) {
                        __half h0 = __float2half_rn(v0);
                        __half h1 = __float2half_rn(v1);
                        *(__half2*)(Ch + (size_t)r * ldc + c) =
                            __halves2half2(h0, h1);
                        if (dup != nullptr)
                            *(float2*)(dup + (size_t)r * 256 + c) =
                                make_float2(__half2float(h0), __half2float(h1));
                    } else {
                        *(float2*)(Cf + (size_t)r * ldc + c) = make_float2(v0, v1);
                    }
                }
                if (zaux != nullptr && col0 < 256) {
                    float* Zrow = zaux + (size_t)r * 256;
#pragma unroll
                    for (int j = 0; j < 8; j++) {
                        int c = col0 + nbase + j * 8 + 2 * qk;
                        *(float2*)(Zrow + c) = make_float2(0.f, 0.f);
                    }
                }
            }
        }
    }
}

// ---------------------------------------------------------------------------
// Preamble: convert weights to K-pair-interleaved half2 words + x to half.
// Block map: [0,192) Wab | [192,288) msg2 | [288,480) up1 | [480,576) up2 |
// [576,592) node | [592,608) tok | [608,3733) x.
// ---------------------------------------------------------------------------
__global__ __launch_bounds__(256) void cvt_all(
    const float* __restrict__ msg_w1, const float* __restrict__ msg_w2,
    const float* __restrict__ up_w1,  const float* __restrict__ up_w2,
    const float* __restrict__ node_w, const float* __restrict__ tok_w1,
    const float* __restrict__ x,
    unsigned* __restrict__ Wh, __half* __restrict__ Xh)
{
    const int b = blockIdx.x;
    const int t = threadIdx.x;

    if (b >= 608) {                      // x: 800000 groups of 8 halves
        int q = (b - 608) * 256 + t;
        float4 a = *(const float4*)(x + (size_t)q * 8);
        float4 c = *(const float4*)(x + (size_t)q * 8 + 4);
        __half2 h[4] = { __floats2half2_rn(a.x, a.y), __floats2half2_rn(a.z, a.w),
                         __floats2half2_rn(c.x, c.y), __floats2half2_rn(c.z, c.w) };
        *(uint4*)(Xh + (size_t)q * 8) = *(uint4*)h;
        return;
    }

    const float *r0, *r1;
    unsigned* dst;
    if (b < 192) {                       // Wab: 3 x [256][512], split msg_w1
        int q = b * 256 + t;             // < 49152
        int l   = q >> 14;
        int rem = q & 16383;
        int kp  = rem >> 7;
        int n0  = (rem & 127) << 2;
        const float* base = msg_w1 + (size_t)l * 544 * 256;
        int k0 = 2 * kp;
        if (n0 < 256) {
            r0 = base + (size_t)k0 * 256 + n0;
            r1 = base + (size_t)(k0 + 1) * 256 + n0;
        } else {
            r0 = base + (size_t)(256 + k0) * 256 + (n0 - 256);
            r1 = base + (size_t)(256 + k0 + 1) * 256 + (n0 - 256);
        }
        dst = Wh + WH_MSGAB + (size_t)((l * 128 + kp) * 512 + n0);
    } else if (b < 288) {                // msg_w2 flat [768][256]
        int q = (b - 192) * 256 + t;
        int kp = q >> 6, n0 = (q & 63) << 2;
        r0 = msg_w2 + (size_t)(2 * kp) * 256 + n0;
        r1 = msg_w2 + (size_t)(2 * kp + 1) * 256 + n0;
        dst = Wh + WH_MSG2 + (size_t)(kp * 256 + n0);
    } else if (b < 480) {                // up_w1 flat [1536][256]
        int q = (b - 288) * 256 + t;
        int kp = q >> 6, n0 = (q & 63) << 2;
        r0 = up_w1 + (size_t)(2 * kp) * 256 + n0;
        r1 = up_w1 + (size_t)(2 * kp + 1) * 256 + n0;
        dst = Wh + WH_UP1 + (size_t)(kp * 256 + n0);
    } else if (b < 576) {                // up_w2 flat [768][256]
        int q = (b - 480) * 256 + t;
        int kp = q >> 6, n0 = (q & 63) << 2;
        r0 = up_w2 + (size_t)(2 * kp) * 256 + n0;
        r1 = up_w2 + (size_t)(2 * kp + 1) * 256 + n0;
        dst = Wh + WH_UP2 + (size_t)(kp * 256 + n0);
    } else if (b < 592) {                // node_w [128][256]
        int q = (b - 576) * 256 + t;
        int kp = q >> 6, n0 = (q & 63) << 2;
        r0 = node_w + (size_t)(2 * kp) * 256 + n0;
        r1 = node_w + (size_t)(2 * kp + 1) * 256 + n0;
        dst = Wh + WH_NODE + (size_t)(kp * 256 + n0);
    } else {                             // tok_w1 [256][128]
        int q = (b - 592) * 256 + t;
        int kp = q >> 5, n0 = (q & 31) << 2;
        r0 = tok_w1 + (size_t)(2 * kp) * 128 + n0;
        r1 = tok_w1 + (size_t)(2 * kp + 1) * 128 + n0;
        dst = Wh + WH_TOK + (size_t)(kp * 128 + n0);
    }
    float4 a = *(const float4*)r0;
    float4 c = *(const float4*)r1;
    __half2 h0 = __floats2half2_rn(a.x, c.x);
    __half2 h1 = __floats2half2_rn(a.y, c.y);
    __half2 h2 = __floats2half2_rn(a.z, c.z);
    __half2 h3 = __floats2half2_rn(a.w, c.w);
    ((__half2*)dst)[0] = h0; ((__half2*)dst)[1] = h1;
    ((__half2*)dst)[2] = h2; ((__half2*)dst)[3] = h3;
}
#define CVT_ALL_BLOCKS 3733

// aggr fp32 -> half into Hcat[:, 256:512]
__global__ void cvt_aggr(const float* __restrict__ Aggr,
                         __half* __restrict__ Hcat, int N)
{
    int idx = blockIdx.x * blockDim.x + threadIdx.x;
    if (idx < N * 64) {
        int r = idx >> 6, c = (idx & 63) << 2;
        float4 v = *(const float4*)(Aggr + (size_t)r * 256 + c);
        __half2 h[2] = { __floats2half2_rn(v.x, v.y), __floats2half2_rn(v.z, v.w) };
        *(uint2*)(Hcat + (size_t)r * 512 + 256 + c) = *(uint2*)h;
    }
}

// ---------------------------------------------------------------------------
// hidden1[e, :] = half(relu( Pa[dst[e]] + Pb[src[e]] + ebuf[e]·Wc + b1 ))
// P is HALF (gather traffic halved). ET=32 edges/block, 2x unrolled.
// ---------------------------------------------------------------------------
#define ET 32
__global__ __launch_bounds__(256) void hidden1_kernel(
    const __half* __restrict__ P,    // [N, 512] = [Pa | Pb] half
    const float* __restrict__ Ebuf,
    const float* __restrict__ Wc,
    const float* __restrict__ b1,
    const int* __restrict__ src,
    const int* __restrict__ dst,
    __half* __restrict__ out,
    int E)
{
    const int j = threadIdx.x;
    const int e0 = blockIdx.x * ET;
    __shared__ float esm[ET][32];
    __shared__ int sdst[ET], ssrc[ET];

    float wc[32];
#pragma unroll
    for (int k = 0; k < 32; k++) wc[k] = Wc[k * 256 + j];

    const int ne = min(ET, E - e0);
    if (j < ne) sdst[j] = dst[e0 + j];
    else if (j >= 64 && j < 64 + ne) ssrc[j - 64] = src[e0 + (j - 64)];
    for (int t = j; t < ne * 32; t += 256)
        esm[t >> 5][t & 31] = Ebuf[(size_t)e0 * 32 + t];
    __syncthreads();

    const float bj = b1[j];
    for (int i = 0; i < ne; i += 2) {
        float acc0 = bj + __half2float(P[(size_t)sdst[i] * 512 + j])
                        + __half2float(P[(size_t)ssrc[i] * 512 + 256 + j]);
        float acc1 = 0.f;
        const bool two = (i + 1 < ne);
        if (two)
            acc1 = bj + __half2float(P[(size_t)sdst[i + 1] * 512 + j])
                      + __half2float(P[(size_t)ssrc[i + 1] * 512 + 256 + j]);
#pragma unroll
        for (int k = 0; k < 32; k++) {
            acc0 = fmaf(esm[i][k], wc[k], acc0);
            if (two) acc1 = fmaf(esm[i + 1][k], wc[k], acc1);
        }
        out[(size_t)(e0 + i) * 256 + j] = __float2half_rn(fmaxf(acc0, 0.f));
        if (two)
            out[(size_t)(e0 + i + 1) * 256 + j] = __float2half_rn(fmaxf(acc1, 0.f));
    }
}

// ---------------------------------------------------------------------------
__global__ __launch_bounds__(256) void edge_proj(
    const float* __restrict__ ea, const float* __restrict__ W,
    const float* __restrict__ b, float* __restrict__ out, int E)
{
    __shared__ float Ws[1024];
    __shared__ float es[8][32];
    const int t = threadIdx.x;
    for (int i = t; i < 1024; i += 256) Ws[i] = W[i];
    const int e0 = blockIdx.x * 8;
    const int ne = min(8, E - e0);
    for (int i = t; i < ne * 32; i += 256)
        es[i >> 5][i & 31] = ea[(size_t)e0 * 32 + i];
    __syncthreads();
    const int el = t >> 5, c = t & 31;
    if (el < ne) {
        float acc = b[c];
#pragma unroll
        for (int k = 0; k < 32; k++) acc = fmaf(es[el][k], Ws[k * 32 + c], acc);
        out[(size_t)(e0 + el) * 32 + c] = acc;
    }
}

__global__ void head2(const float* __restrict__ T, const float* __restrict__ w2,
                      const float* __restrict__ b2, float* __restrict__ out, int N)
{
    int gw = (blockIdx.x * blockDim.x + threadIdx.x) >> 5;
    int lane = threadIdx.x & 31;
    if (gw >= N) return;
    const float* row = T + (size_t)gw * 128;
    float s = 0.f;
#pragma unroll
    for (int k = lane; k < 128; k += 32) s = fmaf(row[k], w2[k], s);
#pragma unroll
    for (int o = 16; o; o >>= 1) s += __shfl_xor_sync(0xFFFFFFFFu, s, o);
    if (lane == 0) out[gw] = s + b2[0];
}

// ---------------------------------------------------------------------------
extern "C" void kernel_launch(void* const* d_in, const int* in_sizes, int n_in,
                              void* d_out, int out_size)
{
    const float* x       = (const float*)d_in[0];
    const int*   ei      = (const int*)d_in[1];
    const float* ea      = (const float*)d_in[2];
    const float* node_w  = (const float*)d_in[3];
    const float* node_b  = (const float*)d_in[4];
    const float* edge_w  = (const float*)d_in[5];
    const float* edge_b  = (const float*)d_in[6];
    const float* msg_w1  = (const float*)d_in[7];
    const float* msg_b1  = (const float*)d_in[8];
    const float* msg_w2  = (const float*)d_in[9];
    const float* msg_b2  = (const float*)d_in[10];
    const float* up_w1   = (const float*)d_in[11];
    const float* up_b1   = (const float*)d_in[12];
    const float* up_w2   = (const float*)d_in[13];
    const float* up_b2   = (const float*)d_in[14];
    const float* tok_w1  = (const float*)d_in[15];
    const float* tok_b1  = (const float*)d_in[16];
    const float* tok_w2  = (const float*)d_in[17];
    const float* tok_b2  = (const float*)d_in[18];

    const int N = in_sizes[0] / 128;   // 50000
    const int E = in_sizes[2] / 32;    // 400000
    const int* src = ei;
    const int* dst = ei + E;

    __half *Hcat, *Ph, *M1, *U, *Xh;
    float *Aggr, *Eb, *T;
    unsigned* Wh;
    cudaGetSymbolAddress((void**)&Hcat, g_Hcat);
    cudaGetSymbolAddress((void**)&Aggr, g_Aggr);
    cudaGetSymbolAddress((void**)&Ph,   g_Ph);
    cudaGetSymbolAddress((void**)&M1,   g_M1);
    cudaGetSymbolAddress((void**)&U,    g_U);
    cudaGetSymbolAddress((void**)&Eb,   g_E);
    cudaGetSymbolAddress((void**)&T,    g_T);
    cudaGetSymbolAddress((void**)&Xh,   g_Xh);
    cudaGetSymbolAddress((void**)&Wh,   g_Wh);

    float* out_logits = (float*)d_out;
    float* out_h      = out_logits + N;

    const int mbN = (N + 127) / 128;   // 391
    const int mbE = (E + 127) / 128;   // 3125

    // ALL instantiations used below must get the smem opt-in.
    cudaFuncSetAttribute(h16gemm<false, false, true >, cudaFuncAttributeMaxDynamicSharedMemorySize, SMEM_BYTES);
    cudaFuncSetAttribute(h16gemm<true,  true,  false>, cudaFuncAttributeMaxDynamicSharedMemorySize, SMEM_BYTES);
    cudaFuncSetAttribute(h16gemm<true,  false, true >, cudaFuncAttributeMaxDynamicSharedMemorySize, SMEM_BYTES);
    cudaFuncSetAttribute(h16gemm<true,  false, false>, cudaFuncAttributeMaxDynamicSharedMemorySize, SMEM_BYTES);

    // ---- preamble: pack weights (K-pair half2) + convert x ----
    cvt_all<<<CVT_ALL_BLOCKS, 256>>>(msg_w1, msg_w2, up_w1, up_w2,
                                     node_w, tok_w1, x, Wh, Xh);

    // h = x @ node_w + node_b -> Hcat[:, 0:256] (half)
    h16gemm<false, false, true><<<dim3(2, mbN), 256, SMEM_BYTES>>>(
        Xh, 128, Wh + WH_NODE, 256, node_b, nullptr, Hcat, 512, N, 128,
        nullptr, nullptr, nullptr);
    // e = edge_attr @ edge_w + edge_b
    edge_proj<<<(E + 7) / 8, 256>>>(ea, edge_w, edge_b, Eb, E);

    for (int l = 0; l < 3; l++) {
        // [Pa | Pb] = h @ Wab -> Ph (HALF); col0<256 blocks zero g_Aggr
        h16gemm<false, false, true><<<dim3(4, mbN), 256, SMEM_BYTES>>>(
            Hcat, 512, Wh + WH_MSGAB + (size_t)l * 65536, 512,
            nullptr, nullptr, Ph, 512, N, 256, nullptr, Aggr, nullptr);
        // hidden1 = half(relu(Pa[dst] + Pb[src] + e@Wc + b1)) -> M1
        hidden1_kernel<<<(E + ET - 1) / ET, 256>>>(
            Ph, Eb, msg_w1 + (size_t)l * 544 * 256 + 512 * 256,
            msg_b1 + l * 256, src, dst, M1, E);
        // m = relu(M1 @ W2 + b2); Aggr[dst] += m  (fused scatter, fp32)
        h16gemm<true, true, false><<<dim3(2, mbE), 256, SMEM_BYTES>>>(
            M1, 256, Wh + WH_MSG2 + (size_t)l * 32768, 256,
            msg_b2 + l * 256, Aggr, nullptr, 256, E, 256, dst, nullptr, nullptr);
        // aggr fp32 -> half into Hcat[:, 256:512]
        cvt_aggr<<<(N * 64 + 255) / 256, 256>>>(Aggr, Hcat, N);
        // u = relu([h|aggr] @ up_w1 + b1) -> U (half)
        h16gemm<true, false, true><<<dim3(2, mbN), 256, SMEM_BYTES>>>(
            Hcat, 512, Wh + WH_UP1 + (size_t)l * 65536, 256,
            up_b1 + l * 256, nullptr, U, 256, N, 512, nullptr, nullptr, nullptr);
        // h = relu(u @ up_w2 + b2) -> Hcat[:, 0:256]; last layer also -> out_h
        h16gemm<true, false, true><<<dim3(2, mbN), 256, SMEM_BYTES>>>(
            U, 256, Wh + WH_UP2 + (size_t)l * 32768, 256,
            up_b2 + l * 256, nullptr, Hcat, 512, N, 256, nullptr, nullptr,
            (l == 2) ? out_h : nullptr);
    }

    // token head: T = relu(h @ tok_w1 + b1) (fp32 out)
    h16gemm<true, false, false><<<dim3(1, mbN), 256, SMEM_BYTES>>>(
        Hcat, 512, Wh + WH_TOK, 128, tok_b1, T, nullptr, 128, N, 256,
        nullptr, nullptr, nullptr);
    head2<<<(N * 32 + 255) / 256, 256>>>(T, tok_w2, tok_b2, out_logits, N);
}